// round 2
// baseline (speedup 1.0000x reference)
#include <cuda_runtime.h>

#define H 512
#define B 128
#define T 1024
#define NCLS 10

#define GRID_MAIN 128
#define TPB 256
#define BT 32          // batch tile per block
#define JT 16          // hidden-column tile per block
#define HS_STRIDE 514  // padded smem row stride for h (floats)

#define SMEM_FLOATS (JT*4*H + BT*HS_STRIDE)   // 32768 + 16448 = 49216
#define SMEM_BYTES  (SMEM_FLOATS * 4)         // 196864

// ---------------- device scratch (static, no allocation) ----------------
__device__ float g_Wpack[H * 4 * H];     // [j][gate][k]  (4 MB)
__device__ float g_xT[T * B];            // transposed x  (512 KB)
__device__ float g_h[2][B * H];          // ping-pong hidden state [b][k]
__device__ unsigned g_cnt;
__device__ volatile unsigned g_gen;

// ---------------- helpers ----------------
__device__ __forceinline__ unsigned long long fma2(unsigned long long a,
                                                   unsigned long long b,
                                                   unsigned long long c) {
    unsigned long long d;
    asm("fma.rn.f32x2 %0, %1, %2, %3;" : "=l"(d) : "l"(a), "l"(b), "l"(c));
    return d;
}

__device__ __forceinline__ float hadd2(unsigned long long a) {
    union { unsigned long long u; float2 f; } x;
    x.u = a;
    return x.f.x + x.f.y;
}

__device__ __forceinline__ float sigf(float x) {
    return 1.0f / (1.0f + expf(-x));
}

// ---------------- setup kernels ----------------
__global__ void lstm_init(const float* __restrict__ x) {
    int i = blockIdx.x * blockDim.x + threadIdx.x;
    if (i < T * B) {
        int t = i >> 7;      // / B
        int b = i & (B - 1);
        g_xT[i] = x[b * T + t];
    }
    if (i < B * H) g_h[0][i] = 0.f;
    if (i == 0) { g_cnt = 0; g_gen = 0; }
}

__global__ void lstm_pack(const float* __restrict__ Wg, const float* __restrict__ Wi,
                          const float* __restrict__ Wf, const float* __restrict__ Wo) {
    int o = blockIdx.x * blockDim.x + threadIdx.x;   // < H*4*H
    int k = o & (H - 1);
    int g = (o >> 9) & 3;
    int j = o >> 11;
    const float* src = (g == 0) ? Wg : (g == 1) ? Wi : (g == 2) ? Wf : Wo;
    g_Wpack[o] = src[k * H + j];
}

// ---------------- main persistent recurrence kernel ----------------
__global__ void __launch_bounds__(TPB, 1)
lstm_main(const float* __restrict__ Wgx, const float* __restrict__ bg,
          const float* __restrict__ Wix, const float* __restrict__ bi,
          const float* __restrict__ Wfx, const float* __restrict__ bf,
          const float* __restrict__ Wox, const float* __restrict__ bo) {
    extern __shared__ float smem[];
    float* Ws = smem;                 // [JT][4][H]
    float* hs = smem + JT * 4 * H;    // [BT][HS_STRIDE]

    const int tid = threadIdx.x;
    const int bt  = blockIdx.x >> 5;      // 0..3
    const int jt  = blockIdx.x & 31;      // 0..31
    const int b0  = bt * BT;
    const int j0  = jt * JT;
    const int jp  = tid >> 5;             // 0..7  (j-pair index)
    const int bl  = tid & 31;             // 0..31 (batch within tile)
    const int b   = b0 + bl;
    const int jg0 = j0 + 2 * jp;

    // --- stage W tile (time-invariant) into smem, coalesced ---
    {
        const float4* src = (const float4*)(g_Wpack + (size_t)j0 * 4 * H);
        float4* dst = (float4*)Ws;
#pragma unroll
        for (int i = 0; i < (JT * 4 * H / 4) / TPB; i++)   // 32 iters
            dst[tid + i * TPB] = src[tid + i * TPB];
    }

    // per-thread input-projection weights / biases for my two j columns
    const float wgx0 = Wgx[jg0], wgx1 = Wgx[jg0 + 1];
    const float bg0  = bg[jg0],  bg1  = bg[jg0 + 1];
    const float wix0 = Wix[jg0], wix1 = Wix[jg0 + 1];
    const float bi0  = bi[jg0],  bi1  = bi[jg0 + 1];
    const float wfx0 = Wfx[jg0], wfx1 = Wfx[jg0 + 1];
    const float bf0  = bf[jg0],  bf1  = bf[jg0 + 1];
    const float wox0 = Wox[jg0], wox1 = Wox[jg0 + 1];
    const float bo0  = bo[jg0],  bo1  = bo[jg0 + 1];

    const float* w0   = Ws + (2 * jp)     * 4 * H;   // [gate][k] for j = jg0
    const float* w1   = Ws + (2 * jp + 1) * 4 * H;   // for j = jg0+1
    const float* hrow = hs + bl * HS_STRIDE;

    float c0 = 0.f, c1 = 0.f;

    __syncthreads();   // Ws ready

    for (int t = 0; t < T; t++) {
        const float* hread  = g_h[t & 1];
        float*       hwrite = g_h[(t + 1) & 1];

        // --- stage h[b0..b0+BT) rows into smem (coalesced, L2-coherent) ---
        {
            const float4* src = (const float4*)(hread + b0 * H);
#pragma unroll
            for (int i = 0; i < (BT * H / 4) / TPB; i++) {   // 16 iters
                int idx = tid + i * TPB;
                int bb  = idx >> 7;       // / (H/4)
                int q   = idx & 127;
                float4 v = __ldcg(src + idx);
                *(float2*)(hs + bb * HS_STRIDE + q * 4)     = make_float2(v.x, v.y);
                *(float2*)(hs + bb * HS_STRIDE + q * 4 + 2) = make_float2(v.z, v.w);
            }
        }
        __syncthreads();

        // --- 4-gate GEMM inner loop: f32x2 lanes = (k even, k odd) ---
        unsigned long long a00 = 0, a01 = 0, a02 = 0, a03 = 0;
        unsigned long long a10 = 0, a11 = 0, a12 = 0, a13 = 0;
#pragma unroll 8
        for (int kp = 0; kp < H / 2; kp++) {
            unsigned long long hh = *(const unsigned long long*)(hrow + 2 * kp);
            a00 = fma2(hh, *(const unsigned long long*)(w0 + 0 * H + 2 * kp), a00);
            a01 = fma2(hh, *(const unsigned long long*)(w0 + 1 * H + 2 * kp), a01);
            a02 = fma2(hh, *(const unsigned long long*)(w0 + 2 * H + 2 * kp), a02);
            a03 = fma2(hh, *(const unsigned long long*)(w0 + 3 * H + 2 * kp), a03);
            a10 = fma2(hh, *(const unsigned long long*)(w1 + 0 * H + 2 * kp), a10);
            a11 = fma2(hh, *(const unsigned long long*)(w1 + 1 * H + 2 * kp), a11);
            a12 = fma2(hh, *(const unsigned long long*)(w1 + 2 * H + 2 * kp), a12);
            a13 = fma2(hh, *(const unsigned long long*)(w1 + 3 * H + 2 * kp), a13);
        }

        const float xv = g_xT[t * B + b];

        float pg0 = hadd2(a00) + xv * wgx0 + bg0;
        float pi0 = hadd2(a01) + xv * wix0 + bi0;
        float pf0 = hadd2(a02) + xv * wfx0 + bf0;
        float po0 = hadd2(a03) + xv * wox0 + bo0;
        float pg1 = hadd2(a10) + xv * wgx1 + bg1;
        float pi1 = hadd2(a11) + xv * wix1 + bi1;
        float pf1 = hadd2(a12) + xv * wfx1 + bf1;
        float po1 = hadd2(a13) + xv * wox1 + bo1;

        float gg0 = tanhf(pg0), ii0 = sigf(pi0), ff0 = sigf(pf0), oo0 = sigf(po0);
        float gg1 = tanhf(pg1), ii1 = sigf(pi1), ff1 = sigf(pf1), oo1 = sigf(po1);

        c0 = gg0 * ii0 + c0 * ff0;
        c1 = gg1 * ii1 + c1 * ff1;
        float h0 = tanhf(c0) * oo0;
        float h1 = tanhf(c1) * oo1;

        *(float2*)(hwrite + b * H + jg0) = make_float2(h0, h1);

        // --- grid barrier: stores -> L2, then arrive/spin ---
        __threadfence();
        __syncthreads();
        if (tid == 0) {
            if (atomicAdd(&g_cnt, 1) == (unsigned)(gridDim.x - 1)) {
                g_cnt = 0;
                __threadfence();
                g_gen = (unsigned)(t + 1);
            } else {
                while (g_gen < (unsigned)(t + 1)) { }
            }
        }
        __syncthreads();
    }
}

// ---------------- final projection: out = h_T @ W_ph^T + b_p ----------------
__global__ void lstm_out(const float* __restrict__ Wph, const float* __restrict__ bp,
                         float* __restrict__ out) {
    __shared__ float hsm[H];
    const int b = blockIdx.x;
    const float* hrow = g_h[0] + b * H;   // T=1024 steps -> final state in buffer 0
    for (int i = threadIdx.x; i < H; i += blockDim.x) hsm[i] = hrow[i];
    __syncthreads();
    const int w = threadIdx.x >> 5, lane = threadIdx.x & 31;
    if (w < NCLS) {
        const float* wr = Wph + w * H;
        float s = 0.f;
        for (int j = lane; j < H; j += 32) s += hsm[j] * wr[j];
#pragma unroll
        for (int off = 16; off; off >>= 1) s += __shfl_down_sync(0xffffffff, s, off);
        if (lane == 0) out[b * NCLS + w] = s + bp[w];
    }
}

// ---------------- launch ----------------
extern "C" void kernel_launch(void* const* d_in, const int* in_sizes, int n_in,
                              void* d_out, int out_size) {
    const float* x   = (const float*)d_in[0];
    const float* Wgx = (const float*)d_in[1];
    const float* Wgh = (const float*)d_in[2];
    const float* bg  = (const float*)d_in[3];
    const float* Wix = (const float*)d_in[4];
    const float* Wih = (const float*)d_in[5];
    const float* bi  = (const float*)d_in[6];
    const float* Wfx = (const float*)d_in[7];
    const float* Wfh = (const float*)d_in[8];
    const float* bf  = (const float*)d_in[9];
    const float* Wox = (const float*)d_in[10];
    const float* Woh = (const float*)d_in[11];
    const float* bo  = (const float*)d_in[12];
    const float* Wph = (const float*)d_in[13];
    const float* bp  = (const float*)d_in[14];
    float* out = (float*)d_out;

    cudaFuncSetAttribute(lstm_main, cudaFuncAttributeMaxDynamicSharedMemorySize,
                         SMEM_BYTES);

    lstm_init<<<(T * B + 255) / 256, 256>>>(x);
    lstm_pack<<<(H * 4 * H) / 256, 256>>>(Wgh, Wih, Wfh, Woh);
    lstm_main<<<GRID_MAIN, TPB, SMEM_BYTES>>>(Wgx, bg, Wix, bi, Wfx, bf, Wox, bo);
    lstm_out<<<B, 320>>>(Wph, bp, out);
}

// round 3
// speedup vs baseline: 1.2108x; 1.2108x over previous
#include <cuda_runtime.h>

#define H 512
#define B 128
#define T 1024
#define NCLS 10

#define GRID_MAIN 128
#define TPB 128
#define BT 32          // batch tile per block
#define JT 16          // hidden-column tile per block
#define WROW 2052      // padded W row stride per j (4*H + 4 floats)
#define HS 516         // padded smem row stride for h (floats)

#define SMEM_FLOATS (JT*WROW + BT*HS)   // 32832 + 16512 = 49344
#define SMEM_BYTES  (SMEM_FLOATS * 4)   // 197376

typedef unsigned long long ull;

// ---------------- device scratch (static, no allocation) ----------------
__device__ float g_Wpack[H * 4 * H];     // [j][gate][k]  (4 MB)
__device__ float g_xT[T * B];            // transposed x
__device__ float g_h[2][B * H];          // ping-pong hidden state [b][k]
__device__ unsigned g_cnt;
__device__ volatile unsigned g_gen;

// ---------------- helpers ----------------
__device__ __forceinline__ ull fma2(ull a, ull b, ull c) {
    ull d;
    asm("fma.rn.f32x2 %0, %1, %2, %3;" : "=l"(d) : "l"(a), "l"(b), "l"(c));
    return d;
}

__device__ __forceinline__ float hadd2(ull a) {
    union { ull u; float2 f; } x;
    x.u = a;
    return x.f.x + x.f.y;
}

__device__ __forceinline__ float sigf(float x) {
    return 1.0f / (1.0f + expf(-x));
}

// ---------------- setup kernels ----------------
__global__ void lstm_init(const float* __restrict__ x) {
    int i = blockIdx.x * blockDim.x + threadIdx.x;
    if (i < T * B) {
        int t = i >> 7;      // / B
        int b = i & (B - 1);
        g_xT[i] = x[b * T + t];
    }
    if (i < B * H) g_h[0][i] = 0.f;
    if (i == 0) { g_cnt = 0; g_gen = 0; }
}

__global__ void lstm_pack(const float* __restrict__ Wg, const float* __restrict__ Wi,
                          const float* __restrict__ Wf, const float* __restrict__ Wo) {
    int o = blockIdx.x * blockDim.x + threadIdx.x;   // < H*4*H
    int k = o & (H - 1);
    int g = (o >> 9) & 3;
    int j = o >> 11;
    const float* src = (g == 0) ? Wg : (g == 1) ? Wi : (g == 2) ? Wf : Wo;
    g_Wpack[o] = src[k * H + j];
}

// ---------------- main persistent recurrence kernel ----------------
__global__ void __launch_bounds__(TPB, 1)
lstm_main(const float* __restrict__ Wgx, const float* __restrict__ bg,
          const float* __restrict__ Wix, const float* __restrict__ bi,
          const float* __restrict__ Wfx, const float* __restrict__ bf,
          const float* __restrict__ Wox, const float* __restrict__ bo) {
    extern __shared__ float smem[];
    float* Ws = smem;                 // [JT][4*H + 4 pad]
    float* hs = smem + JT * WROW;     // [BT][HS]

    const int tid = threadIdx.x;
    const int bt  = blockIdx.x >> 5;      // 0..3
    const int jt  = blockIdx.x & 31;      // 0..31
    const int b0  = bt * BT;
    const int j0  = jt * JT;
    const int jp  = tid >> 4;             // 0..7  (j-pair index)
    const int bq  = tid & 15;             // 0..15
    const int bA  = b0 + bq;
    const int bB  = bA + 16;
    const int jg0 = j0 + 2 * jp;

    // --- stage W tile (time-invariant) into padded smem rows ---
    {
#pragma unroll
        for (int i = 0; i < 64; i++) {            // 16 rows * 512 float4 / 128 thr
            int idx = tid + i * TPB;
            int jl  = idx >> 9;                   // / 512
            int q   = idx & 511;
            *(float4*)(Ws + jl * WROW + q * 4) =
                *(const float4*)(g_Wpack + (size_t)(j0 + jl) * (4 * H) + q * 4);
        }
    }

    // per-thread input-projection weights / biases for my two j columns
    float wx[2][4], bsv[2][4];
#pragma unroll
    for (int ji = 0; ji < 2; ji++) {
        int j = jg0 + ji;
        wx[ji][0] = Wgx[j]; wx[ji][1] = Wix[j]; wx[ji][2] = Wfx[j]; wx[ji][3] = Wox[j];
        bsv[ji][0] = bg[j]; bsv[ji][1] = bi[j]; bsv[ji][2] = bf[j]; bsv[ji][3] = bo[j];
    }

    const float* wp0 = Ws + (2 * jp) * WROW;      // j = jg0
    const float* wp1 = wp0 + WROW;                // j = jg0+1
    const float* hpA = hs + bq * HS;
    const float* hpB = hpA + 16 * HS;

    float c00 = 0.f, c01 = 0.f, c10 = 0.f, c11 = 0.f;

    __syncthreads();   // Ws ready

    for (int t = 0; t < T; t++) {
        const float* hread  = g_h[t & 1];
        float*       hwrite = g_h[(t + 1) & 1];

        // --- stage h[b0..b0+BT) into padded smem rows (L2-coherent) ---
        {
            const float4* src = (const float4*)(hread + b0 * H);
#pragma unroll
            for (int i = 0; i < 32; i++) {        // 32*512/4 = 4096 f4 / 128 thr
                int idx = tid + i * TPB;
                int bb  = idx >> 7;               // / 128 f4-per-row
                int q   = idx & 127;
                float4 v = __ldcg(src + idx);
                *(float4*)(hs + bb * HS + q * 4) = v;
            }
        }
        __syncthreads();

        // --- 2b x 2j x 4g register tile, f32x2 over k, LDS.128 ---
        ull acc[16];     // [bi*8 + ji*4 + g]
#pragma unroll
        for (int i = 0; i < 16; i++) acc[i] = 0ull;

#pragma unroll 4
        for (int kq = 0; kq < H / 4; kq++) {
            const int ko = 4 * kq;
            ulonglong2 va = *(const ulonglong2*)(hpA + ko);
            ulonglong2 vb = *(const ulonglong2*)(hpB + ko);
#pragma unroll
            for (int g = 0; g < 4; g++) {
                ulonglong2 w0 = *(const ulonglong2*)(wp0 + g * H + ko);
                ulonglong2 w1 = *(const ulonglong2*)(wp1 + g * H + ko);
                acc[0 + g]  = fma2(va.x, w0.x, acc[0 + g]);
                acc[0 + g]  = fma2(va.y, w0.y, acc[0 + g]);
                acc[4 + g]  = fma2(va.x, w1.x, acc[4 + g]);
                acc[4 + g]  = fma2(va.y, w1.y, acc[4 + g]);
                acc[8 + g]  = fma2(vb.x, w0.x, acc[8 + g]);
                acc[8 + g]  = fma2(vb.y, w0.y, acc[8 + g]);
                acc[12 + g] = fma2(vb.x, w1.x, acc[12 + g]);
                acc[12 + g] = fma2(vb.y, w1.y, acc[12 + g]);
            }
        }

        const float xA = g_xT[t * B + bA];
        const float xB = g_xT[t * B + bB];

        float h00, h01, h10, h11;
        {
            float pg = hadd2(acc[0]) + xA * wx[0][0] + bsv[0][0];
            float pi = hadd2(acc[1]) + xA * wx[0][1] + bsv[0][1];
            float pf = hadd2(acc[2]) + xA * wx[0][2] + bsv[0][2];
            float po = hadd2(acc[3]) + xA * wx[0][3] + bsv[0][3];
            float gv = tanhf(pg), iv = sigf(pi), fv = sigf(pf), ov = sigf(po);
            c00 = gv * iv + c00 * fv;  h00 = tanhf(c00) * ov;
        }
        {
            float pg = hadd2(acc[4]) + xA * wx[1][0] + bsv[1][0];
            float pi = hadd2(acc[5]) + xA * wx[1][1] + bsv[1][1];
            float pf = hadd2(acc[6]) + xA * wx[1][2] + bsv[1][2];
            float po = hadd2(acc[7]) + xA * wx[1][3] + bsv[1][3];
            float gv = tanhf(pg), iv = sigf(pi), fv = sigf(pf), ov = sigf(po);
            c01 = gv * iv + c01 * fv;  h01 = tanhf(c01) * ov;
        }
        {
            float pg = hadd2(acc[8])  + xB * wx[0][0] + bsv[0][0];
            float pi = hadd2(acc[9])  + xB * wx[0][1] + bsv[0][1];
            float pf = hadd2(acc[10]) + xB * wx[0][2] + bsv[0][2];
            float po = hadd2(acc[11]) + xB * wx[0][3] + bsv[0][3];
            float gv = tanhf(pg), iv = sigf(pi), fv = sigf(pf), ov = sigf(po);
            c10 = gv * iv + c10 * fv;  h10 = tanhf(c10) * ov;
        }
        {
            float pg = hadd2(acc[12]) + xB * wx[1][0] + bsv[1][0];
            float pi = hadd2(acc[13]) + xB * wx[1][1] + bsv[1][1];
            float pf = hadd2(acc[14]) + xB * wx[1][2] + bsv[1][2];
            float po = hadd2(acc[15]) + xB * wx[1][3] + bsv[1][3];
            float gv = tanhf(pg), iv = sigf(pi), fv = sigf(pf), ov = sigf(po);
            c11 = gv * iv + c11 * fv;  h11 = tanhf(c11) * ov;
        }

        *(float2*)(hwrite + bA * H + jg0) = make_float2(h00, h01);
        *(float2*)(hwrite + bB * H + jg0) = make_float2(h10, h11);

        // --- grid barrier: stores -> L2, then arrive/spin ---
        __threadfence();
        __syncthreads();
        if (tid == 0) {
            if (atomicAdd(&g_cnt, 1) == (unsigned)(gridDim.x - 1)) {
                g_cnt = 0;
                __threadfence();
                g_gen = (unsigned)(t + 1);
            } else {
                while (g_gen < (unsigned)(t + 1)) { }
            }
        }
        __syncthreads();
    }
}

// ---------------- final projection: out = h_T @ W_ph^T + b_p ----------------
__global__ void lstm_out(const float* __restrict__ Wph, const float* __restrict__ bp,
                         float* __restrict__ out) {
    __shared__ float hsm[H];
    const int b = blockIdx.x;
    const float* hrow = g_h[0] + b * H;   // T=1024 even -> final state in buffer 0
    for (int i = threadIdx.x; i < H; i += blockDim.x) hsm[i] = hrow[i];
    __syncthreads();
    const int w = threadIdx.x >> 5, lane = threadIdx.x & 31;
    if (w < NCLS) {
        const float* wr = Wph + w * H;
        float s = 0.f;
        for (int j = lane; j < H; j += 32) s += hsm[j] * wr[j];
#pragma unroll
        for (int off = 16; off; off >>= 1) s += __shfl_down_sync(0xffffffff, s, off);
        if (lane == 0) out[b * NCLS + w] = s + bp[w];
    }
}

// ---------------- launch ----------------
extern "C" void kernel_launch(void* const* d_in, const int* in_sizes, int n_in,
                              void* d_out, int out_size) {
    const float* x   = (const float*)d_in[0];
    const float* Wgx = (const float*)d_in[1];
    const float* Wgh = (const float*)d_in[2];
    const float* bg  = (const float*)d_in[3];
    const float* Wix = (const float*)d_in[4];
    const float* Wih = (const float*)d_in[5];
    const float* bi  = (const float*)d_in[6];
    const float* Wfx = (const float*)d_in[7];
    const float* Wfh = (const float*)d_in[8];
    const float* bf  = (const float*)d_in[9];
    const float* Wox = (const float*)d_in[10];
    const float* Woh = (const float*)d_in[11];
    const float* bo  = (const float*)d_in[12];
    const float* Wph = (const float*)d_in[13];
    const float* bp  = (const float*)d_in[14];
    float* out = (float*)d_out;

    cudaFuncSetAttribute(lstm_main, cudaFuncAttributeMaxDynamicSharedMemorySize,
                         SMEM_BYTES);

    lstm_init<<<(T * B + 255) / 256, 256>>>(x);
    lstm_pack<<<(H * 4 * H) / 256, 256>>>(Wgh, Wih, Wfh, Woh);
    lstm_main<<<GRID_MAIN, TPB, SMEM_BYTES>>>(Wgx, bg, Wix, bi, Wfx, bf, Wox, bo);
    lstm_out<<<B, 320>>>(Wph, bp, out);
}

// round 4
// speedup vs baseline: 1.2247x; 1.0115x over previous
#include <cuda_runtime.h>

#define H 512
#define B 128
#define T 1024
#define NCLS 10

#define GRID_MAIN 128
#define TPB 256
#define BT 32          // batch tile per block
#define JT 16          // hidden-column tile per block
#define GS 516         // padded smem stride per gate row (floats)
#define WJ (4*GS)      // per-j W row (4 gates)
#define HS 516         // padded smem row stride for h (floats)

#define SMEM_FLOATS (JT*WJ + BT*HS)     // 33024 + 16512 = 49536
#define SMEM_BYTES  (SMEM_FLOATS * 4)   // 198144

typedef unsigned long long ull;

// ---------------- device scratch (static, no allocation) ----------------
__device__ float g_Wpack[H * 4 * H];     // [j][gate][k]  (4 MB)
__device__ float g_xT[T * B];            // transposed x
__device__ float g_h[2][B * H];          // ping-pong hidden state [b][k]
__device__ unsigned g_cnt4[4];
__device__ unsigned g_gen4[4];

// ---------------- helpers ----------------
__device__ __forceinline__ ull fma2(ull a, ull b, ull c) {
    ull d;
    asm("fma.rn.f32x2 %0, %1, %2, %3;" : "=l"(d) : "l"(a), "l"(b), "l"(c));
    return d;
}

__device__ __forceinline__ float hadd2(ull a) {
    union { ull u; float2 f; } x;
    x.u = a;
    return x.f.x + x.f.y;
}

// fast sigmoid / tanh via MUFU-based __expf (rel err ~1e-6)
__device__ __forceinline__ float sigf(float x) {
    return __fdividef(1.0f, 1.0f + __expf(-x));
}
__device__ __forceinline__ float tanf_(float x) {
    return __fdividef(2.0f, 1.0f + __expf(-2.0f * x)) - 1.0f;
}

// ---------------- setup kernels ----------------
__global__ void lstm_init(const float* __restrict__ x) {
    int i = blockIdx.x * blockDim.x + threadIdx.x;
    if (i < T * B) {
        int t = i >> 7;      // / B
        int b = i & (B - 1);
        g_xT[i] = x[b * T + t];
    }
    if (i < B * H) g_h[0][i] = 0.f;
    if (i < 4) { g_cnt4[i] = 0; g_gen4[i] = 0; }
}

__global__ void lstm_pack(const float* __restrict__ Wg, const float* __restrict__ Wi,
                          const float* __restrict__ Wf, const float* __restrict__ Wo) {
    int o = blockIdx.x * blockDim.x + threadIdx.x;   // < H*4*H
    int k = o & (H - 1);
    int g = (o >> 9) & 3;
    int j = o >> 11;
    const float* src = (g == 0) ? Wg : (g == 1) ? Wi : (g == 2) ? Wf : Wo;
    g_Wpack[o] = src[k * H + j];   // [j][gate][k]
}

// ---------------- main persistent recurrence kernel ----------------
__global__ void __launch_bounds__(TPB, 1)
lstm_main(const float* __restrict__ Wgx, const float* __restrict__ bg,
          const float* __restrict__ Wix, const float* __restrict__ bi,
          const float* __restrict__ Wfx, const float* __restrict__ bf,
          const float* __restrict__ Wox, const float* __restrict__ bo) {
    extern __shared__ float smem[];
    float* Ws = smem;                 // [JT][4][GS]
    float* hs = smem + JT * WJ;       // [BT][HS]

    const int tid   = threadIdx.x;
    const int bt    = blockIdx.x >> 5;     // 0..3 (barrier group)
    const int jt    = blockIdx.x & 31;     // 0..31
    const int b0    = bt * BT;
    const int j0    = jt * JT;
    const int jp    = tid >> 5;            // warp id = j-pair 0..7
    const int lane  = tid & 31;
    const int gpair = lane >> 4;           // 0: gates {g,i}, 1: gates {f,o}
    const int bq    = lane & 15;
    const int bA    = b0 + bq;
    const int bB    = bA + 16;
    const int j_own = j0 + 2 * jp + gpair; // j column this thread finalizes

    // --- stage W tile (time-invariant) into padded smem rows ---
#pragma unroll
    for (int i = 0; i < 32; i++) {             // 8192 float4 / 256 thr
        int idx = tid + i * TPB;
        int jl  = idx >> 9;                    // 512 f4 per j
        int r   = idx & 511;
        int g   = r >> 7;
        int q   = r & 127;
        *(float4*)(Ws + jl * WJ + g * GS + q * 4) =
            *(const float4*)(g_Wpack + (size_t)(j0 + jl) * (4 * H) + g * H + q * 4);
    }

    // per-thread input-projection weights / biases for j_own (all 4 gates)
    const float wxg = Wgx[j_own], wxi = Wix[j_own], wxf = Wfx[j_own], wxo = Wox[j_own];
    const float bvg = bg[j_own],  bvi = bi[j_own],  bvf = bf[j_own],  bvo = bo[j_own];

    const float* wbase = Ws + (2 * jp) * WJ + gpair * (2 * GS);  // my 2 gates, j=jg0
    const float* hpA   = hs + bq * HS;
    const float* hpB   = hpA + 16 * HS;

    float cA = 0.f, cB = 0.f;

    unsigned* cnt = &g_cnt4[bt];
    unsigned* gen = &g_gen4[bt];

    __syncthreads();   // Ws ready

    for (int t = 0; t < T; t++) {
        const float* hread  = g_h[t & 1];
        float*       hwrite = g_h[(t + 1) & 1];

        // --- stage h[b0..b0+BT) into padded smem rows (L2-coherent) ---
        {
            const float4* src = (const float4*)(hread + b0 * H);
#pragma unroll
            for (int i = 0; i < 16; i++) {     // 4096 f4 / 256 thr
                int idx = tid + i * TPB;
                int bb  = idx >> 7;
                int q   = idx & 127;
                float4 v = __ldcg(src + idx);
                *(float4*)(hs + bb * HS + q * 4) = v;
            }
        }
        __syncthreads();

        // --- 2b x 2j x 2g register tile, f32x2 over k, LDS.128 ---
        ull acc[8];    // [b*4 + jl*2 + gl]
#pragma unroll
        for (int i = 0; i < 8; i++) acc[i] = 0ull;

#pragma unroll 4
        for (int kq = 0; kq < H / 4; kq++) {
            const int ko = 4 * kq;
            ulonglong2 va = *(const ulonglong2*)(hpA + ko);
            ulonglong2 vb = *(const ulonglong2*)(hpB + ko);
#pragma unroll
            for (int jl = 0; jl < 2; jl++) {
#pragma unroll
                for (int gl = 0; gl < 2; gl++) {
                    ulonglong2 w = *(const ulonglong2*)(wbase + jl * WJ + gl * GS + ko);
                    int ia = jl * 2 + gl;
                    acc[ia]     = fma2(va.x, w.x, acc[ia]);
                    acc[ia]     = fma2(va.y, w.y, acc[ia]);
                    acc[4 + ia] = fma2(vb.x, w.x, acc[4 + ia]);
                    acc[4 + ia] = fma2(vb.y, w.y, acc[4 + ia]);
                }
            }
        }

        float p[8];
#pragma unroll
        for (int i = 0; i < 8; i++) p[i] = hadd2(acc[i]);

        // exchange the gate-pair computed for the OTHER j with the partner lane
        const int jo = (1 - gpair) * 2;   // offset of "other j" partials
        const int jm = gpair * 2;         // offset of my-j partials
        float rA0 = __shfl_xor_sync(0xffffffffu, p[jo + 0],     16);
        float rA1 = __shfl_xor_sync(0xffffffffu, p[jo + 1],     16);
        float rB0 = __shfl_xor_sync(0xffffffffu, p[4 + jo + 0], 16);
        float rB1 = __shfl_xor_sync(0xffffffffu, p[4 + jo + 1], 16);

        // assemble (g,i,f,o) pre-activations for j_own
        float gA = gpair ? rA0 : p[jm + 0];
        float iA = gpair ? rA1 : p[jm + 1];
        float fA = gpair ? p[jm + 0] : rA0;
        float oA = gpair ? p[jm + 1] : rA1;
        float gB = gpair ? rB0 : p[4 + jm + 0];
        float iB = gpair ? rB1 : p[4 + jm + 1];
        float fB = gpair ? p[4 + jm + 0] : rB0;
        float oB = gpair ? p[4 + jm + 1] : rB1;

        const float xA = __ldg(g_xT + t * B + bA);
        const float xB = __ldg(g_xT + t * B + bB);

        float gvA = tanf_(gA + xA * wxg + bvg);
        float ivA = sigf (iA + xA * wxi + bvi);
        float fvA = sigf (fA + xA * wxf + bvf);
        float ovA = sigf (oA + xA * wxo + bvo);
        cA = gvA * ivA + cA * fvA;
        float hAv = tanf_(cA) * ovA;

        float gvB = tanf_(gB + xB * wxg + bvg);
        float ivB = sigf (iB + xB * wxi + bvi);
        float fvB = sigf (fB + xB * wxf + bvf);
        float ovB = sigf (oB + xB * wxo + bvo);
        cB = gvB * ivB + cB * fvB;
        float hBv = tanf_(cB) * ovB;

        hwrite[bA * H + j_own] = hAv;
        hwrite[bB * H + j_own] = hBv;

        // --- group barrier (32 blocks sharing bt): release/acquire, tid 0 only ---
        __syncthreads();
        if (tid == 0) {
            unsigned old;
            asm volatile("atom.add.acq_rel.gpu.global.u32 %0, [%1], 1;"
                         : "=r"(old) : "l"(cnt) : "memory");
            if (old == 31u) {
                asm volatile("st.relaxed.gpu.global.u32 [%0], %1;"
                             :: "l"(cnt), "r"(0u) : "memory");
                asm volatile("st.release.gpu.global.u32 [%0], %1;"
                             :: "l"(gen), "r"((unsigned)(t + 1)) : "memory");
            } else {
                unsigned v;
                do {
                    asm volatile("ld.acquire.gpu.global.u32 %0, [%1];"
                                 : "=r"(v) : "l"(gen) : "memory");
                } while (v < (unsigned)(t + 1));
            }
        }
        __syncthreads();
    }
}

// ---------------- final projection: out = h_T @ W_ph^T + b_p ----------------
__global__ void lstm_out(const float* __restrict__ Wph, const float* __restrict__ bp,
                         float* __restrict__ out) {
    __shared__ float hsm[H];
    const int b = blockIdx.x;
    const float* hrow = g_h[0] + b * H;   // T=1024 even -> final state in buffer 0
    for (int i = threadIdx.x; i < H; i += blockDim.x) hsm[i] = hrow[i];
    __syncthreads();
    const int w = threadIdx.x >> 5, lane = threadIdx.x & 31;
    if (w < NCLS) {
        const float* wr = Wph + w * H;
        float s = 0.f;
        for (int j = lane; j < H; j += 32) s += hsm[j] * wr[j];
#pragma unroll
        for (int off = 16; off; off >>= 1) s += __shfl_down_sync(0xffffffff, s, off);
        if (lane == 0) out[b * NCLS + w] = s + bp[w];
    }
}

// ---------------- launch ----------------
extern "C" void kernel_launch(void* const* d_in, const int* in_sizes, int n_in,
                              void* d_out, int out_size) {
    const float* x   = (const float*)d_in[0];
    const float* Wgx = (const float*)d_in[1];
    const float* Wgh = (const float*)d_in[2];
    const float* bg  = (const float*)d_in[3];
    const float* Wix = (const float*)d_in[4];
    const float* Wih = (const float*)d_in[5];
    const float* bi  = (const float*)d_in[6];
    const float* Wfx = (const float*)d_in[7];
    const float* Wfh = (const float*)d_in[8];
    const float* bf  = (const float*)d_in[9];
    const float* Wox = (const float*)d_in[10];
    const float* Woh = (const float*)d_in[11];
    const float* bo  = (const float*)d_in[12];
    const float* Wph = (const float*)d_in[13];
    const float* bp  = (const float*)d_in[14];
    float* out = (float*)d_out;

    cudaFuncSetAttribute(lstm_main, cudaFuncAttributeMaxDynamicSharedMemorySize,
                         SMEM_BYTES);

    lstm_init<<<(T * B + 255) / 256, 256>>>(x);
    lstm_pack<<<(H * 4 * H) / 256, 256>>>(Wgh, Wih, Wfh, Woh);
    lstm_main<<<GRID_MAIN, TPB, SMEM_BYTES>>>(Wgx, bg, Wix, bi, Wfx, bf, Wox, bo);
    lstm_out<<<B, 320>>>(Wph, bp, out);
}